// round 3
// baseline (speedup 1.0000x reference)
#include <cuda_runtime.h>

#define KK    15
#define PADK  7
#define TW    128
#define TH    64
#define TROWS (TH + 2 * PADK)   // 78
#define HH    512
#define WW    512
#define CH    3

__global__ __launch_bounds__(256)
void gauss_blur_kernel(const float* __restrict__ xin_all,
                       const float* __restrict__ sigma,
                       float* __restrict__ out_all)
{
    __shared__ __align__(16) float temp[TROWS][TW];   // 78 * 128 * 4 = 39936 B
    __shared__ float wsh[KK];

    const int bc = blockIdx.z;          // b * C + c
    const int b  = bc / CH;

    // --- per-batch separable weights: w_i = g_i / sqrt(S^2 + 1e-8) ---
    if (threadIdx.x == 0) {
        float s  = sigma[b];
        float s2 = 2.0f * s * s + 1e-8f;
        float g[KK];
        float S = 0.0f;
        #pragma unroll
        for (int i = 0; i < KK; i++) {
            float d = (float)(i - PADK);
            g[i] = expf(-(d * d) / s2);
            S += g[i];
        }
        float inv = rsqrtf(S * S + 1e-8f);
        #pragma unroll
        for (int i = 0; i < KK; i++) wsh[i] = g[i] * inv;
    }
    __syncthreads();

    float wl[KK];
    #pragma unroll
    for (int i = 0; i < KK; i++) wl[i] = wsh[i];

    const float* __restrict__ img    = xin_all + (size_t)bc * HH * WW;
    float*       __restrict__ outimg = out_all + (size_t)bc * HH * WW;
    const int y0 = blockIdx.y * TH;
    const int x0 = blockIdx.x * TW;

    // ---------------- Phase 1: horizontal conv into shared ----------------
    {
        const int xg  = threadIdx.x & 15;   // 16 groups of 8 outputs across TW=128
        const int ry  = threadIdx.x >> 4;   // 16 row-lanes
        const int gx0 = x0 + xg * 8 - PADK;

        for (int r = ry; r < TROWS; r += 16) {
            const int gy = y0 - PADK + r;
            float in[8 + KK - 1];           // 22-wide register window
            if ((unsigned)gy < (unsigned)HH) {
                const float* row = img + (size_t)gy * WW;
                #pragma unroll
                for (int i = 0; i < 22; i++) {
                    int gx = gx0 + i;
                    in[i] = ((unsigned)gx < (unsigned)WW) ? __ldg(row + gx) : 0.0f;
                }
            } else {
                #pragma unroll
                for (int i = 0; i < 22; i++) in[i] = 0.0f;
            }

            float acc[8];
            #pragma unroll
            for (int j = 0; j < 8; j++) {
                float a = 0.0f;
                #pragma unroll
                for (int k = 0; k < KK; k++)
                    a = fmaf(wl[k], in[j + k], a);
                acc[j] = a;
            }

            // vectorized stores (scalar stride-8 stores would 8-way bank conflict)
            float4* dst = reinterpret_cast<float4*>(&temp[r][xg * 8]);
            dst[0] = make_float4(acc[0], acc[1], acc[2], acc[3]);
            dst[1] = make_float4(acc[4], acc[5], acc[6], acc[7]);
        }
    }
    __syncthreads();

    // ---------------- Phase 2: vertical conv, write out ----------------
    {
        const int xv = threadIdx.x & 31;    // 32 float4 columns = 128 floats
        const int ty = threadIdx.x >> 5;    // 8 row-lanes

        #pragma unroll
        for (int oy = ty; oy < TH; oy += 8) {
            float4 a = make_float4(0.0f, 0.0f, 0.0f, 0.0f);
            #pragma unroll
            for (int k = 0; k < KK; k++) {
                float4 v = *reinterpret_cast<const float4*>(&temp[oy + k][xv * 4]);
                a.x = fmaf(wl[k], v.x, a.x);
                a.y = fmaf(wl[k], v.y, a.y);
                a.z = fmaf(wl[k], v.z, a.z);
                a.w = fmaf(wl[k], v.w, a.w);
            }
            *reinterpret_cast<float4*>(outimg + (size_t)(y0 + oy) * WW + x0 + xv * 4) = a;
        }
    }
}

extern "C" void kernel_launch(void* const* d_in, const int* in_sizes, int n_in,
                              void* d_out, int out_size)
{
    const float* x     = (const float*)d_in[0];
    const float* sigma = (const float*)d_in[1];
    float*       out   = (float*)d_out;

    const int B = in_sizes[1];                 // sigma has one entry per batch
    dim3 grid(WW / TW, HH / TH, B * CH);       // (4, 8, 96)
    gauss_blur_kernel<<<grid, 256>>>(x, sigma, out);
}

// round 5
// speedup vs baseline: 1.9583x; 1.9583x over previous
#include <cuda_runtime.h>

#define KK    15
#define PADK  7
#define TW    128
#define TH    64
#define TROWS (TH + 2 * PADK)   // 78
#define HH    512
#define WW    512
#define CH    3

__global__ __launch_bounds__(256)
void gauss_blur_kernel(const float* __restrict__ xin_all,
                       const float* __restrict__ sigma,
                       float* __restrict__ out_all)
{
    __shared__ __align__(16) float temp[TROWS][TW];   // 39936 B
    __shared__ float wsh[KK];

    const int bc = blockIdx.z;          // b * C + c
    const int b  = bc / CH;

    // --- per-batch separable weights: w_i = g_i / sqrt(S^2 + 1e-8) ---
    if (threadIdx.x == 0) {
        float s  = sigma[b];
        float s2 = 2.0f * s * s + 1e-8f;
        float g[KK];
        float S = 0.0f;
        #pragma unroll
        for (int i = 0; i < KK; i++) {
            float d = (float)(i - PADK);
            g[i] = expf(-(d * d) / s2);
            S += g[i];
        }
        float inv = rsqrtf(S * S + 1e-8f);
        #pragma unroll
        for (int i = 0; i < KK; i++) wsh[i] = g[i] * inv;
    }
    __syncthreads();

    float wl[KK];
    #pragma unroll
    for (int i = 0; i < KK; i++) wl[i] = wsh[i];

    const float* __restrict__ img    = xin_all + (size_t)bc * HH * WW;
    float*       __restrict__ outimg = out_all + (size_t)bc * HH * WW;
    const int y0 = blockIdx.y * TH;
    const int x0 = blockIdx.x * TW;

    // ---------------- Phase 1: horizontal conv into shared ----------------
    // 16 x-groups of 8 outputs x 16 row-lanes. Aligned 24-float window via 6x float4.
    {
        const int xg   = threadIdx.x & 15;
        const int ry   = threadIdx.x >> 4;
        const int gx0a = x0 + xg * 8 - 8;        // 32B-aligned window start
        // taps for output j (j=0..7) are in[1 + j + k], k=0..14

        for (int r = ry; r < TROWS; r += 16) {
            const int gy = y0 - PADK + r;
            float in[24];
            if ((unsigned)gy < (unsigned)HH) {
                const float* row = img + (size_t)gy * WW;
                #pragma unroll
                for (int v = 0; v < 6; v++) {
                    const int gxv = gx0a + v * 4;
                    if ((unsigned)gxv < (unsigned)WW) {   // gxv in [0,508] -> full float4 in-bounds
                        float4 t = *reinterpret_cast<const float4*>(row + gxv);
                        in[v * 4 + 0] = t.x; in[v * 4 + 1] = t.y;
                        in[v * 4 + 2] = t.z; in[v * 4 + 3] = t.w;
                    } else {
                        #pragma unroll
                        for (int e = 0; e < 4; e++) {
                            int gx = gxv + e;
                            in[v * 4 + e] = ((unsigned)gx < (unsigned)WW) ? row[gx] : 0.0f;
                        }
                    }
                }
            } else {
                #pragma unroll
                for (int i = 0; i < 24; i++) in[i] = 0.0f;
            }

            float acc[8];
            #pragma unroll
            for (int j = 0; j < 8; j++) {
                float a = 0.0f;
                #pragma unroll
                for (int k = 0; k < KK; k++)
                    a = fmaf(wl[k], in[1 + j + k], a);
                acc[j] = a;
            }

            float4* dst = reinterpret_cast<float4*>(&temp[r][xg * 8]);
            dst[0] = make_float4(acc[0], acc[1], acc[2], acc[3]);
            dst[1] = make_float4(acc[4], acc[5], acc[6], acc[7]);
        }
    }
    __syncthreads();

    // ---------------- Phase 2: vertical conv with register sliding window ----------------
    // 128 columns x 2 vertical halves of 32 rows. 46 LDS per 32 outputs (1.44/output).
    {
        const int col   = threadIdx.x & 127;
        const int half  = threadIdx.x >> 7;      // 0 or 1
        const int ybase = half * 32;

        float win[KK];                            // ring buffer, constant-indexed after unroll
        #pragma unroll
        for (int i = 0; i < KK; i++) win[i] = temp[ybase + i][col];

        float* ocol = outimg + (size_t)(y0 + ybase) * WW + x0 + col;

        #pragma unroll
        for (int j = 0; j < 32; j++) {
            float a = 0.0f;
            #pragma unroll
            for (int k = 0; k < KK; k++)
                a = fmaf(wl[k], win[(j + k) % KK], a);
            ocol[(size_t)j * WW] = a;
            if (j < 31)
                win[j % KK] = temp[ybase + j + KK][col];
        }
    }
}

extern "C" void kernel_launch(void* const* d_in, const int* in_sizes, int n_in,
                              void* d_out, int out_size)
{
    const float* x     = (const float*)d_in[0];
    const float* sigma = (const float*)d_in[1];
    float*       out   = (float*)d_out;

    const int B = in_sizes[1];                 // sigma has one entry per batch
    dim3 grid(WW / TW, HH / TH, B * CH);       // (4, 8, 96)
    gauss_blur_kernel<<<grid, 256>>>(x, sigma, out);
}